// round 5
// baseline (speedup 1.0000x reference)
#include <cuda_runtime.h>
#include <cuda_bf16.h>
#include <cstdint>
#include <math.h>

// Problem constants (fixed by the dataset)
#define NROWS 200000
#define CCH   256
#define BGR   4
#define GRP   32
#define KTAP  27
#define CEMB  1024
#define EPSV  1e-5f

#define TILE_M    128
#define CHUNKS    8                    // 32-cin chunks per tap
#define NITER     (KTAP * CHUNKS)      // 216
#define NBLK_CONV ((NROWS + TILE_M - 1) / TILE_M)   // 1563

// packed row: 8 chunks x [32 hi bf16 (64B) | 32 lo bf16 (64B)] = 1024 B/row
#define ROWB   1024
#define ASTAGE 16384                   // 128 slots * 128B
#define BSTAGE 32768                   // 256 couts * 128B
#define STAGE  (ASTAGE + BSTAGE)       // 48KB per stage
#define CBYTES (TILE_M * CCH * 4)      // 128KB fp32 C tile in smem

// -------- scratch (static __device__ — no runtime allocation) --------
__device__ unsigned char g_xp[(size_t)NROWS * ROWB];        // 204.8 MB packed acts
__device__ unsigned char g_w1p[(size_t)KTAP * CCH * 1024];  // 6.9 MB packed weights
__device__ unsigned char g_w2p[(size_t)KTAP * CCH * 1024];
__device__ float g_sum[BGR * CCH];
__device__ float g_sq[BGR * CCH];
__device__ float g_mean[BGR * GRP];
__device__ float g_rstd[BGR * GRP];
__device__ int   g_cnt[BGR];
__device__ float g_ss[BGR * 2 * CCH];

// ---------------------------------------------------------------------
__device__ __forceinline__ float silu_f(float v) { return v / (1.0f + expf(-v)); }

__device__ __forceinline__ uint32_t s2u(const void* p) {
    return (uint32_t)__cvta_generic_to_shared(p);
}
__device__ __forceinline__ void cp16(uint32_t dst, const void* src) {
    asm volatile("cp.async.cg.shared.global [%0], [%1], 16;" :: "r"(dst), "l"(src));
}
__device__ __forceinline__ void sts16_zero(uint32_t dst) {
    asm volatile("st.shared.v4.b32 [%0], {%1,%1,%1,%1};" :: "r"(dst), "r"(0u) : "memory");
}
__device__ __forceinline__ void ldsm4(uint32_t* r, uint32_t a) {
    asm volatile("ldmatrix.sync.aligned.m8n8.x4.shared.b16 {%0,%1,%2,%3}, [%4];"
                 : "=r"(r[0]), "=r"(r[1]), "=r"(r[2]), "=r"(r[3]) : "r"(a));
}
__device__ __forceinline__ void mma_bf16(float* d, const uint32_t* a,
                                         uint32_t b0, uint32_t b1) {
    asm volatile(
        "mma.sync.aligned.m16n8k16.row.col.f32.bf16.bf16.f32 "
        "{%0,%1,%2,%3}, {%4,%5,%6,%7}, {%8,%9}, {%0,%1,%2,%3};"
        : "+f"(d[0]), "+f"(d[1]), "+f"(d[2]), "+f"(d[3])
        : "r"(a[0]), "r"(a[1]), "r"(a[2]), "r"(a[3]), "r"(b0), "r"(b1));
}
__device__ __forceinline__ void lds_v2(float& x, float& y, uint32_t a) {
    asm volatile("ld.shared.v2.f32 {%0,%1}, [%2];" : "=f"(x), "=f"(y) : "r"(a));
}
__device__ __forceinline__ void sts_v2(uint32_t a, float x, float y) {
    asm volatile("st.shared.v2.f32 [%0], {%1,%2};" :: "r"(a), "f"(x), "f"(y) : "memory");
}
__device__ __forceinline__ void lds_v4(float4& v, uint32_t a) {
    asm volatile("ld.shared.v4.f32 {%0,%1,%2,%3}, [%4];"
                 : "=f"(v.x), "=f"(v.y), "=f"(v.z), "=f"(v.w) : "r"(a));
}

__device__ __forceinline__ void split_bf16(float v, __nv_bfloat16& h, __nv_bfloat16& l) {
    h = __float2bfloat16(v);
    l = __float2bfloat16(v - __bfloat162float(h));
}
__device__ __forceinline__ uint32_t pack2(__nv_bfloat16 a, __nv_bfloat16 b) {
    __nv_bfloat162 p = __halves2bfloat162(a, b);
    return *reinterpret_cast<uint32_t*>(&p);
}

// -------- per-grid voxel counts (g_cnt zeroed by finalize phase 2) --------
__global__ void count_kernel(const int* __restrict__ jidx, int n) {
    int c0 = 0, c1 = 0, c2 = 0, c3 = 0;
    for (int i = blockIdx.x * blockDim.x + threadIdx.x; i < n;
         i += gridDim.x * blockDim.x) {
        int b = jidx[i];
        c0 += (b == 0); c1 += (b == 1); c2 += (b == 2); c3 += (b == 3);
    }
    if (c0) atomicAdd(&g_cnt[0], c0);
    if (c1) atomicAdd(&g_cnt[1], c1);
    if (c2) atomicAdd(&g_cnt[2], c2);
    if (c3) atomicAdd(&g_cnt[3], c3);
}

__global__ void stats_kernel(const float* __restrict__ x,
                             const int* __restrict__ jidx, int nrows) {
    const int t = threadIdx.x;                 // channel, blockDim = 256
    int r0 = blockIdx.x * 512;
    int r1 = r0 + 512; if (r1 > nrows) r1 = nrows;
    float s = 0.0f, sq = 0.0f; int cur = -1;
    for (int r = r0; r < r1; ++r) {
        int b = jidx[r];
        if (b != cur) {
            if (cur >= 0) {
                atomicAdd(&g_sum[cur * CCH + t], s);
                atomicAdd(&g_sq[cur * CCH + t], sq);
            }
            cur = b; s = 0.0f; sq = 0.0f;
        }
        float v = x[(size_t)r * CCH + t];
        s += v; sq += v * v;
    }
    if (cur >= 0) {
        atomicAdd(&g_sum[cur * CCH + t], s);
        atomicAdd(&g_sq[cur * CCH + t], sq);
    }
}

// phase 1: compute mean/rstd, zero g_sum/g_sq for the next stats pass.
// phase 2: same + zero g_cnt (restores pristine state for next graph replay).
__global__ void finalize_kernel(int phase) {
    int t = threadIdx.x;                       // blockDim = 128
    if (t < BGR * GRP) {
        int b = t / GRP, g = t % GRP;
        float s = 0.0f, sq = 0.0f;
        #pragma unroll
        for (int j = 0; j < 8; ++j) {
            s  += g_sum[b * CCH + g * 8 + j];
            sq += g_sq [b * CCH + g * 8 + j];
        }
        float denom = (float)g_cnt[b] * 8.0f;
        float mean = s / denom;
        float var  = sq / denom - mean * mean;
        g_mean[t] = mean;
        g_rstd[t] = rsqrtf(var + EPSV);
    }
    __syncthreads();
    for (int i = t; i < BGR * CCH; i += 128) { g_sum[i] = 0.0f; g_sq[i] = 0.0f; }
    if (phase == 2 && t < BGR) g_cnt[t] = 0;
}

// -------- GN + SiLU -> packed bf16 hi/lo rows (film=0: GN1; film=1: GN2+FiLM) --
__global__ void norm_pack_kernel(const float* __restrict__ x,
                                 const int* __restrict__ jidx,
                                 const float* __restrict__ w,
                                 const float* __restrict__ bb,
                                 unsigned char* __restrict__ xp, int film) {
    size_t i4 = (size_t)blockIdx.x * blockDim.x + threadIdx.x;
    if (i4 >= (size_t)NROWS * (CCH / 4)) return;
    int n = (int)(i4 >> 6);
    int c = ((int)i4 & 63) * 4;
    int b = jidx[n];
    int g = c >> 3;
    float mean = g_mean[b * GRP + g];
    float rstd = g_rstd[b * GRP + g];
    float4 xv = *(const float4*)(x + i4 * 4);
    float4 wv = *(const float4*)(w + c);
    float4 bv = *(const float4*)(bb + c);
    float o[4];
    o[0] = (xv.x - mean) * rstd * wv.x + bv.x;
    o[1] = (xv.y - mean) * rstd * wv.y + bv.y;
    o[2] = (xv.z - mean) * rstd * wv.z + bv.z;
    o[3] = (xv.w - mean) * rstd * wv.w + bv.w;
    if (film) {
        float4 sc = *(const float4*)(g_ss + b * (2 * CCH) + c);
        float4 sh = *(const float4*)(g_ss + b * (2 * CCH) + CCH + c);
        o[0] = o[0] * (1.0f + sc.x) + sh.x;
        o[1] = o[1] * (1.0f + sc.y) + sh.y;
        o[2] = o[2] * (1.0f + sc.z) + sh.z;
        o[3] = o[3] * (1.0f + sc.w) + sh.w;
    }
    __nv_bfloat16 h[4], l[4];
    #pragma unroll
    for (int j = 0; j < 4; ++j) {
        float s = silu_f(o[j]);
        split_bf16(s, h[j], l[j]);
    }
    size_t base = (size_t)n * ROWB + (size_t)(c >> 5) * 128 + (size_t)(c & 31) * 2;
    uint2 hv = make_uint2(pack2(h[0], h[1]), pack2(h[2], h[3]));
    uint2 lv = make_uint2(pack2(l[0], l[1]), pack2(l[2], l[3]));
    *(uint2*)(xp + base)      = hv;
    *(uint2*)(xp + base + 64) = lv;
}

// -------- pack W[k][cin][cout] -> wp[(k*256+cout)*8 + cin/32][32hi|32lo] ------
__global__ void wpack_kernel(const float* __restrict__ W,
                             unsigned char* __restrict__ wp) {
    int bid = blockIdx.x;               // 0 .. 27*256-1
    int k = bid >> 8, cout = bid & 255;
    int cin = threadIdx.x;              // 0..255
    float v = W[((size_t)(k * CCH + cin)) * CCH + cout];
    __nv_bfloat16 h, l;
    split_bf16(v, h, l);
    size_t base = ((size_t)(k * CCH + cout) * 8 + (cin >> 5)) * 128 + (size_t)(cin & 31) * 2;
    *(__nv_bfloat16*)(wp + base)      = h;
    *(__nv_bfloat16*)(wp + base + 64) = l;
}

// -------- embedding MLP --------
__global__ void emb_kernel(const float* __restrict__ emb,
                           const float* __restrict__ ew,
                           const float* __restrict__ eb) {
    __shared__ float se[CEMB];
    int b = blockIdx.x;
    int t = threadIdx.x;                // blockDim = 512
    for (int i = t; i < CEMB; i += 512) se[i] = silu_f(emb[b * CEMB + i]);
    __syncthreads();
    float acc = eb[t];
    for (int i = 0; i < CEMB; ++i)
        acc += se[i] * ew[i * (2 * CCH) + t];
    g_ss[b * (2 * CCH) + t] = acc;
}

// ================= HMMA sparse-conv GEMM with per-tap row compaction =========
// CTA: 512 thr, 128 out-rows x 256 cout. C lives in smem fp32 (swizzled rows).
// Per tap: ballot-compact valid neighbor rows (~45% occupancy -> ~0.5x MMA
// m-tiles), 3-pass bf16-split MMA over 8 K-chunks into register accs, then
// scatter-add the tap partial into C via the compaction row list.
__global__ void __launch_bounds__(512, 1) convmma_kernel(
    const unsigned char* __restrict__ xp, const int* __restrict__ nbr,
    const unsigned char* __restrict__ wp, const float* __restrict__ bias,
    const float* __restrict__ resid, float* __restrict__ out, int nrows)
{
    extern __shared__ unsigned char dsm[];
    __shared__ int s_idx[2][TILE_M];     // compacted gather indices (ping-pong by tap)
    __shared__ int s_row[2][TILE_M];     // compacted slot -> local out row
    __shared__ int s_v[2];               // valid count
    __shared__ int s_wsum[2][4];

    const int tid  = threadIdx.x;
    const int lane = tid & 31;
    const int wid  = tid >> 5;
    const int wr   = wid & 3;            // warp m-row (owns compacted tiles wr, wr+4)
    const int wn   = wid >> 2;           // warp n-col (64 couts)
    const int row0 = blockIdx.x * TILE_M;

    const uint32_t cbase = (s2u(dsm) + 127u) & ~127u;   // C tile: 128KB
    const uint32_t sbase = cbase + CBYTES;              // 2 stages x 48KB

    // ldmatrix lane decomposition
    const int l7 = lane & 7;
    const int lq = (lane >> 3) & 1;
    const int lh = (lane >> 4) & 1;
    const int tq = lane >> 2;            // 0..7
    const int tr = lane & 3;             // 0..3

    // zero C
    for (int i = tid; i < CBYTES / 16; i += 512) sts16_zero(cbase + i * 16u);

    float acc[2][8][4];
#pragma unroll
    for (int ps = 0; ps < 2; ++ps)
#pragma unroll
        for (int nt = 0; nt < 8; ++nt)
#pragma unroll
            for (int q = 0; q < 4; ++q) acc[ps][nt][q] = 0.0f;

    // ---- per-tap compaction: ballot + warp prefix over local rows ----
    auto compact = [&](int tap) {
        const int par = tap & 1;
        int idxv = -1; bool val = false; int pos = 0;
        if (tid < TILE_M) {
            if (row0 + tid < nrows)
                idxv = nbr[(size_t)(row0 + tid) * KTAP + tap];
            val = idxv >= 0;
            unsigned m = __ballot_sync(0xffffffffu, val);
            pos = __popc(m & ((1u << lane) - 1u));
            if (lane == 0) s_wsum[par][wid] = __popc(m);
        }
        __syncthreads();
        if (tid < TILE_M) {
            int base = 0;
#pragma unroll
            for (int w = 0; w < 4; ++w) if (w < wid) base += s_wsum[par][w];
            if (val) { s_idx[par][base + pos] = idxv; s_row[par][base + pos] = tid; }
            if (tid == 0)
                s_v[par] = s_wsum[par][0] + s_wsum[par][1] + s_wsum[par][2] + s_wsum[par][3];
        }
        __syncthreads();
    };

    // ---- load one (tap, chunk): compacted A slots + full B ----
    auto load_chunk = [&](int j) {
        const int kk = j >> 3, cc = j & 7, buf = j & 1, par = kk & 1;
        const int v    = s_v[par];
        const int vpad = (v + 15) & ~15;
        const int slot = tid >> 2;
        const uint32_t ab = sbase + (uint32_t)buf * STAGE + (uint32_t)slot * 128u;
        if (slot < vpad) {
            const int sidx = (slot < v) ? s_idx[par][slot] : -1;
            if (sidx >= 0) {
                const unsigned char* src = xp + (size_t)sidx * ROWB + (size_t)cc * 128;
#pragma unroll
                for (int u = 0; u < 2; ++u) {
                    int seg = (tid & 3) * 2 + u;
                    cp16(ab + (uint32_t)((seg ^ (slot & 7)) * 16), src + seg * 16);
                }
            } else {
#pragma unroll
                for (int u = 0; u < 2; ++u) {
                    int seg = (tid & 3) * 2 + u;
                    sts16_zero(ab + (uint32_t)((seg ^ (slot & 7)) * 16));
                }
            }
        }
        const int bco = tid >> 1;
        const unsigned char* bsrc = wp + ((size_t)(kk * CCH + bco) * 8 + cc) * 128;
        const uint32_t bb = sbase + (uint32_t)buf * STAGE + ASTAGE + (uint32_t)bco * 128u;
#pragma unroll
        for (int u = 0; u < 4; ++u) {
            int seg = (tid & 1) * 4 + u;
            cp16(bb + (uint32_t)((seg ^ (bco & 7)) * 16), bsrc + seg * 16);
        }
        asm volatile("cp.async.commit_group;");
    };

    // ---- scatter-add tap partial into C, zero accs ----
    auto scatter = [&](int tap) {
        const int par = tap & 1;
        const int v = s_v[par];
        const int mtiles = (v + 15) >> 4;
#pragma unroll
        for (int ps = 0; ps < 2; ++ps) {
            const int gmt = wr + ps * 4;
            if (gmt < mtiles) {
                const int s0 = gmt * 16 + tq;
                const int s1 = s0 + 8;
                const int r0v = (s0 < v) ? s_row[par][s0] : -1;
                const int r1v = (s1 < v) ? s_row[par][s1] : -1;
#pragma unroll
                for (int nt = 0; nt < 8; ++nt) {
                    const int cb = (wn * 64 + nt * 8 + tr * 2) * 4;
                    if (r0v >= 0) {
                        uint32_t a = cbase + (uint32_t)r0v * 1024u
                                   + (uint32_t)(cb ^ ((r0v & 7) << 4));
                        float x, y; lds_v2(x, y, a);
                        sts_v2(a, x + acc[ps][nt][0], y + acc[ps][nt][1]);
                    }
                    if (r1v >= 0) {
                        uint32_t a = cbase + (uint32_t)r1v * 1024u
                                   + (uint32_t)(cb ^ ((r1v & 7) << 4));
                        float x, y; lds_v2(x, y, a);
                        sts_v2(a, x + acc[ps][nt][2], y + acc[ps][nt][3]);
                    }
                }
            }
#pragma unroll
            for (int nt = 0; nt < 8; ++nt)
#pragma unroll
                for (int q = 0; q < 4; ++q) acc[ps][nt][q] = 0.0f;
        }
    };

    // prologue
    compact(0);           // syncs inside also publish zeroed C
    load_chunk(0);

    for (int it = 0; it < NITER; ++it) {
        asm volatile("cp.async.wait_group 0;");
        __syncthreads();                          // stage `it` visible to all

        if (it + 1 < NITER) {
            if (((it + 1) & 7) == 0) compact((it + 1) >> 3);
            load_chunk(it + 1);
        }

        // compute tap chunk `it`
        {
            const int tap = it >> 3, par = tap & 1, buf = it & 1;
            const int v = s_v[par];
            const int mtiles = (v + 15) >> 4;
            if (mtiles > 0) {
                const uint32_t ab = sbase + (uint32_t)buf * STAGE;
                const uint32_t bb = ab + ASTAGE;
#pragma unroll
                for (int ks = 0; ks < 2; ++ks) {
                    uint32_t ah[2][4], al[2][4];
                    bool act[2];
#pragma unroll
                    for (int ps = 0; ps < 2; ++ps) {
                        const int gmt = wr + ps * 4;
                        act[ps] = gmt < mtiles;
                        if (act[ps]) {
                            const int m_r = gmt * 16 + l7 + lq * 8;
                            const int sg  = ks * 2 + lh;
                            const uint32_t rbase = ab + (uint32_t)m_r * 128u;
                            ldsm4(ah[ps], rbase + (uint32_t)(((sg    ) ^ l7) * 16));
                            ldsm4(al[ps], rbase + (uint32_t)(((sg + 4) ^ l7) * 16));
                        }
                    }
#pragma unroll
                    for (int p = 0; p < 4; ++p) {
                        const int n_r = wn * 64 + p * 16 + lh * 8 + l7;
                        const int sg  = ks * 2 + lq;
                        const uint32_t rbase = bb + (uint32_t)n_r * 128u;
                        uint32_t bh[4], bl[4];
                        ldsm4(bh, rbase + (uint32_t)(((sg    ) ^ l7) * 16));
                        ldsm4(bl, rbase + (uint32_t)(((sg + 4) ^ l7) * 16));
#pragma unroll
                        for (int ps = 0; ps < 2; ++ps) {
                            if (!act[ps]) continue;
#pragma unroll
                            for (int q = 0; q < 2; ++q) {
                                float* d = acc[ps][p * 2 + q];
                                mma_bf16(d, ah[ps], bh[2 * q], bh[2 * q + 1]);
                                mma_bf16(d, ah[ps], bl[2 * q], bl[2 * q + 1]);
                                mma_bf16(d, al[ps], bh[2 * q], bh[2 * q + 1]);
                            }
                        }
                    }
                }
            }
            if ((it & 7) == 7) scatter(tap);      // disjoint C rows per warp; no barrier
        }
    }

    // ---- epilogue: C + bias (+resid) -> out ----
    __syncthreads();
    {
        const int erow = tid >> 2;
        const int ec0  = (tid & 3) * 64;
        if (row0 + erow < nrows) {
            const size_t gro = (size_t)(row0 + erow) * CCH;
#pragma unroll
            for (int j = 0; j < 16; ++j) {
                const int c = ec0 + j * 4;
                uint32_t a = cbase + (uint32_t)erow * 1024u
                           + (uint32_t)((c * 4) ^ ((erow & 7) << 4));
                float4 cv; lds_v4(cv, a);
                float4 bv = *(const float4*)(bias + c);
                cv.x += bv.x; cv.y += bv.y; cv.z += bv.z; cv.w += bv.w;
                if (resid) {
                    float4 rv = *(const float4*)(resid + gro + c);
                    cv.x += rv.x; cv.y += rv.y; cv.z += rv.z; cv.w += rv.w;
                }
                *(float4*)(out + gro + c) = cv;
            }
        }
    }
}

// ---------------------------------------------------------------------
extern "C" void kernel_launch(void* const* d_in, const int* in_sizes, int n_in,
                              void* d_out, int out_size)
{
    const float* feats = (const float*)d_in[0];
    const float* emb   = (const float*)d_in[1];
    const int*   jidx  = (const int*)  d_in[2];
    const int*   nbr   = (const int*)  d_in[3];
    const float* gn1w  = (const float*)d_in[4];
    const float* gn1b  = (const float*)d_in[5];
    const float* w1    = (const float*)d_in[6];
    const float* b1    = (const float*)d_in[7];
    const float* embw  = (const float*)d_in[8];
    const float* embb  = (const float*)d_in[9];
    const float* gn2w  = (const float*)d_in[10];
    const float* gn2b  = (const float*)d_in[11];
    const float* w2    = (const float*)d_in[12];
    const float* b2    = (const float*)d_in[13];
    float* out = (float*)d_out;

    unsigned char *xp = nullptr, *w1p = nullptr, *w2p = nullptr;
    cudaGetSymbolAddress((void**)&xp,  g_xp);
    cudaGetSymbolAddress((void**)&w1p, g_w1p);
    cudaGetSymbolAddress((void**)&w2p, g_w2p);

    const int SMEM_CONV = 128 + CBYTES + 2 * STAGE;   // 128 + 128KB + 96KB = 229504
    cudaFuncSetAttribute(convmma_kernel,
                         cudaFuncAttributeMaxDynamicSharedMemorySize, SMEM_CONV);

    const int nblk_norm  = (NROWS * (CCH / 4) + 255) / 256;
    const int nblk_stats = (NROWS + 511) / 512;

    // Launch order puts conv1 at index 5 so ncu (-s 5 -c 1) captures it.
    count_kernel<<<64, 256>>>(jidx, NROWS);                              // 0
    stats_kernel<<<nblk_stats, 256>>>(feats, jidx, NROWS);               // 1
    finalize_kernel<<<1, 128>>>(1);                                      // 2
    norm_pack_kernel<<<nblk_norm, 256>>>(feats, jidx, gn1w, gn1b, xp, 0);// 3
    wpack_kernel<<<KTAP * CCH, 256>>>(w1, w1p);                          // 4
    convmma_kernel<<<NBLK_CONV, 512, SMEM_CONV>>>(xp, nbr, w1p, b1,      // 5
                                                  nullptr, out, NROWS);
    emb_kernel<<<BGR, 512>>>(emb, embw, embb);                           // 6
    stats_kernel<<<nblk_stats, 256>>>(out, jidx, NROWS);                 // 7
    finalize_kernel<<<1, 128>>>(2);                                      // 8
    norm_pack_kernel<<<nblk_norm, 256>>>(out, jidx, gn2w, gn2b, xp, 1);  // 9
    wpack_kernel<<<KTAP * CCH, 256>>>(w2, w2p);                          // 10
    convmma_kernel<<<NBLK_CONV, 512, SMEM_CONV>>>(xp, nbr, w2p, b2,      // 11
                                                  feats, out, NROWS);
}

// round 6
// speedup vs baseline: 1.7149x; 1.7149x over previous
#include <cuda_runtime.h>
#include <cuda_fp16.h>
#include <cstdint>
#include <math.h>

// Problem constants (fixed by the dataset)
#define NROWS 200000
#define CCH   256
#define BGR   4
#define GRP   32
#define KTAP  27
#define CEMB  1024
#define EPSV  1e-5f

#define TILE_M    128
#define CHUNKS    8                    // 32-cin chunks per tap
#define NITER     (KTAP * CHUNKS)      // 216
#define NBLK_CONV ((NROWS + TILE_M - 1) / TILE_M)   // 1563

// packed act row: 8 chunks x [32 hi fp16 (64B) | 32 lo fp16 (64B)] = 1024 B/row
// packed wgt row: 8 chunks x [32 fp16 (64B)] = 512 B per (tap, cout)
#define ROWB   1024
#define ASTAGE 16384                   // 128 rows  * 128B
#define BSTAGE 16384                   // 256 couts *  64B
#define STAGE  (ASTAGE + BSTAGE)       // 32KB per stage
#define NSTAGE 4

// -------- scratch (static __device__ — no runtime allocation) --------
__device__ unsigned char g_xp[(size_t)NROWS * ROWB];        // 204.8 MB packed acts
__device__ unsigned char g_w1p[(size_t)KTAP * CCH * 512];   // 3.5 MB packed weights
__device__ unsigned char g_w2p[(size_t)KTAP * CCH * 512];
__device__ float g_sum[BGR * CCH];
__device__ float g_sq[BGR * CCH];
__device__ float g_mean[BGR * GRP];
__device__ float g_rstd[BGR * GRP];
__device__ int   g_cnt[BGR];
__device__ float g_ss[BGR * 2 * CCH];

// ---------------------------------------------------------------------
__device__ __forceinline__ float silu_f(float v) { return v / (1.0f + expf(-v)); }

__device__ __forceinline__ uint32_t s2u(const void* p) {
    return (uint32_t)__cvta_generic_to_shared(p);
}
__device__ __forceinline__ void cp16(uint32_t dst, const void* src) {
    asm volatile("cp.async.cg.shared.global [%0], [%1], 16;" :: "r"(dst), "l"(src));
}
__device__ __forceinline__ void sts16_zero(uint32_t dst) {
    asm volatile("st.shared.v4.b32 [%0], {%1,%1,%1,%1};" :: "r"(dst), "r"(0u) : "memory");
}
__device__ __forceinline__ void ldsm4(uint32_t* r, uint32_t a) {
    asm volatile("ldmatrix.sync.aligned.m8n8.x4.shared.b16 {%0,%1,%2,%3}, [%4];"
                 : "=r"(r[0]), "=r"(r[1]), "=r"(r[2]), "=r"(r[3]) : "r"(a));
}
__device__ __forceinline__ void mma_f16(float* d, const uint32_t* a,
                                        uint32_t b0, uint32_t b1) {
    asm volatile(
        "mma.sync.aligned.m16n8k16.row.col.f32.f16.f16.f32 "
        "{%0,%1,%2,%3}, {%4,%5,%6,%7}, {%8,%9}, {%0,%1,%2,%3};"
        : "+f"(d[0]), "+f"(d[1]), "+f"(d[2]), "+f"(d[3])
        : "r"(a[0]), "r"(a[1]), "r"(a[2]), "r"(a[3]), "r"(b0), "r"(b1));
}

__device__ __forceinline__ void split_f16(float v, __half& h, __half& l) {
    h = __float2half(v);
    l = __float2half(v - __half2float(h));
}
__device__ __forceinline__ uint32_t pack2h(__half a, __half b) {
    __half2 p = __halves2half2(a, b);
    return *reinterpret_cast<uint32_t*>(&p);
}

// -------- per-grid voxel counts (g_cnt zeroed by finalize phase 2) --------
__global__ void count_kernel(const int* __restrict__ jidx, int n) {
    int c0 = 0, c1 = 0, c2 = 0, c3 = 0;
    for (int i = blockIdx.x * blockDim.x + threadIdx.x; i < n;
         i += gridDim.x * blockDim.x) {
        int b = jidx[i];
        c0 += (b == 0); c1 += (b == 1); c2 += (b == 2); c3 += (b == 3);
    }
    if (c0) atomicAdd(&g_cnt[0], c0);
    if (c1) atomicAdd(&g_cnt[1], c1);
    if (c2) atomicAdd(&g_cnt[2], c2);
    if (c3) atomicAdd(&g_cnt[3], c3);
}

__global__ void stats_kernel(const float* __restrict__ x,
                             const int* __restrict__ jidx, int nrows) {
    const int t = threadIdx.x;                 // channel, blockDim = 256
    int r0 = blockIdx.x * 512;
    int r1 = r0 + 512; if (r1 > nrows) r1 = nrows;
    float s = 0.0f, sq = 0.0f; int cur = -1;
    for (int r = r0; r < r1; ++r) {
        int b = jidx[r];
        if (b != cur) {
            if (cur >= 0) {
                atomicAdd(&g_sum[cur * CCH + t], s);
                atomicAdd(&g_sq[cur * CCH + t], sq);
            }
            cur = b; s = 0.0f; sq = 0.0f;
        }
        float v = x[(size_t)r * CCH + t];
        s += v; sq += v * v;
    }
    if (cur >= 0) {
        atomicAdd(&g_sum[cur * CCH + t], s);
        atomicAdd(&g_sq[cur * CCH + t], sq);
    }
}

// phase 1: mean/rstd + zero g_sum/g_sq for the next stats pass.
// phase 2: same + zero g_cnt (pristine state for next graph replay).
__global__ void finalize_kernel(int phase) {
    int t = threadIdx.x;                       // blockDim = 128
    if (t < BGR * GRP) {
        int b = t / GRP, g = t % GRP;
        float s = 0.0f, sq = 0.0f;
        #pragma unroll
        for (int j = 0; j < 8; ++j) {
            s  += g_sum[b * CCH + g * 8 + j];
            sq += g_sq [b * CCH + g * 8 + j];
        }
        float denom = (float)g_cnt[b] * 8.0f;
        float mean = s / denom;
        float var  = sq / denom - mean * mean;
        g_mean[t] = mean;
        g_rstd[t] = rsqrtf(var + EPSV);
    }
    __syncthreads();
    for (int i = t; i < BGR * CCH; i += 128) { g_sum[i] = 0.0f; g_sq[i] = 0.0f; }
    if (phase == 2 && t < BGR) g_cnt[t] = 0;
}

// -------- GN + SiLU -> packed fp16 hi/lo rows (film=0: GN1; film=1: GN2+FiLM) --
__global__ void norm_pack_kernel(const float* __restrict__ x,
                                 const int* __restrict__ jidx,
                                 const float* __restrict__ w,
                                 const float* __restrict__ bb,
                                 unsigned char* __restrict__ xp, int film) {
    size_t i4 = (size_t)blockIdx.x * blockDim.x + threadIdx.x;
    if (i4 >= (size_t)NROWS * (CCH / 4)) return;
    int n = (int)(i4 >> 6);
    int c = ((int)i4 & 63) * 4;
    int b = jidx[n];
    int g = c >> 3;
    float mean = g_mean[b * GRP + g];
    float rstd = g_rstd[b * GRP + g];
    float4 xv = *(const float4*)(x + i4 * 4);
    float4 wv = *(const float4*)(w + c);
    float4 bv = *(const float4*)(bb + c);
    float o[4];
    o[0] = (xv.x - mean) * rstd * wv.x + bv.x;
    o[1] = (xv.y - mean) * rstd * wv.y + bv.y;
    o[2] = (xv.z - mean) * rstd * wv.z + bv.z;
    o[3] = (xv.w - mean) * rstd * wv.w + bv.w;
    if (film) {
        float4 sc = *(const float4*)(g_ss + b * (2 * CCH) + c);
        float4 sh = *(const float4*)(g_ss + b * (2 * CCH) + CCH + c);
        o[0] = o[0] * (1.0f + sc.x) + sh.x;
        o[1] = o[1] * (1.0f + sc.y) + sh.y;
        o[2] = o[2] * (1.0f + sc.z) + sh.z;
        o[3] = o[3] * (1.0f + sc.w) + sh.w;
    }
    __half h[4], l[4];
    #pragma unroll
    for (int j = 0; j < 4; ++j) {
        float s = silu_f(o[j]);
        split_f16(s, h[j], l[j]);
    }
    size_t base = (size_t)n * ROWB + (size_t)(c >> 5) * 128 + (size_t)(c & 31) * 2;
    uint2 hv = make_uint2(pack2h(h[0], h[1]), pack2h(h[2], h[3]));
    uint2 lv = make_uint2(pack2h(l[0], l[1]), pack2h(l[2], l[3]));
    *(uint2*)(xp + base)      = hv;
    *(uint2*)(xp + base + 64) = lv;
}

// -------- pack W[k][cin][cout] -> wp[(k*256+cout)*8 + cin/32] (64B, fp16) -----
__global__ void wpack_kernel(const float* __restrict__ W,
                             unsigned char* __restrict__ wp) {
    int bid = blockIdx.x;               // 0 .. 27*256-1
    int k = bid >> 8, cout = bid & 255;
    int cin = threadIdx.x;              // 0..255
    float v = W[((size_t)(k * CCH + cin)) * CCH + cout];
    __half h = __float2half(v);
    size_t base = ((size_t)(k * CCH + cout) * 8 + (cin >> 5)) * 64 + (size_t)(cin & 31) * 2;
    *(__half*)(wp + base) = h;
}

// -------- embedding MLP --------
__global__ void emb_kernel(const float* __restrict__ emb,
                           const float* __restrict__ ew,
                           const float* __restrict__ eb) {
    __shared__ float se[CEMB];
    int b = blockIdx.x;
    int t = threadIdx.x;                // blockDim = 512
    for (int i = t; i < CEMB; i += 512) se[i] = silu_f(emb[b * CEMB + i]);
    __syncthreads();
    float acc = eb[t];
    for (int i = 0; i < CEMB; ++i)
        acc += se[i] * ew[i * (2 * CCH) + t];
    g_ss[b * (2 * CCH) + t] = acc;
}

// ================= HMMA sparse-conv GEMM (fp16, 2-pass) =================
// CTA: 512 thr, tile 128 rows x 256 cout. Warp grid 4m x 4n, warp tile 32x64.
// fp32 ~ A(hi+lo fp16) * B(fp16): D = Ah*Bh + Al*Bh  (err ~ A*(B-Bh) ~ 2^-11)
// 4-stage cp.async pipeline, one __syncthreads per iteration:
//   wait_group -> sync -> issue loads(it+3) -> compute(it)
__global__ void __launch_bounds__(512, 1) convmma_kernel(
    const unsigned char* __restrict__ xp, const int* __restrict__ nbr,
    const unsigned char* __restrict__ wp, const float* __restrict__ bias,
    const float* __restrict__ resid, float* __restrict__ out, int nrows)
{
    extern __shared__ unsigned char dsm[];
    const int tid  = threadIdx.x;
    const int lane = tid & 31;
    const int wid  = tid >> 5;
    const int wm   = wid & 3;            // warp m-tile (32 rows each)
    const int wn   = wid >> 2;           // warp n-tile (64 couts each)
    const int row0 = blockIdx.x * TILE_M;

    uint32_t sb = (s2u(dsm) + 127u) & ~127u;

    // ldmatrix lane decomposition
    const int l7 = lane & 7;
    const int lq = (lane >> 3) & 1;
    const int lh = (lane >> 4) & 1;

    // gather mapping: A rows (thread t -> row t>>2, 2 segs of 8),
    //                 B couts (thread t -> cout t>>1, 2 segs of 4)
    const int grow  = tid >> 2;
    const bool gok  = (row0 + grow) < nrows;
    const int aseg0 = (tid & 3) * 2;
    const int bco   = tid >> 1;
    const int bseg0 = (tid & 1) * 2;

    float acc[2][8][4];
#pragma unroll
    for (int mt = 0; mt < 2; ++mt)
#pragma unroll
        for (int nt = 0; nt < 8; ++nt)
#pragma unroll
            for (int q = 0; q < 4; ++q) acc[mt][nt][q] = 0.0f;

    int gidx = -1;
    auto load_chunk = [&](int j) {
        const int kk = j >> 3, cc = j & 7, buf = j & (NSTAGE - 1);
        if (cc == 0) gidx = gok ? nbr[(size_t)(row0 + grow) * KTAP + kk] : -1;
        // A: 128B packed hi|lo chunk, XOR-8 swizzle (row stride 128B)
        const uint32_t ab = sb + buf * STAGE + (uint32_t)grow * 128u;
        if (gidx >= 0) {
            const unsigned char* src = xp + (size_t)gidx * ROWB + (size_t)cc * 128;
#pragma unroll
            for (int u = 0; u < 2; ++u) {
                int seg = aseg0 + u;
                cp16(ab + (uint32_t)((seg ^ (grow & 7)) * 16), src + seg * 16);
            }
        } else {
#pragma unroll
            for (int u = 0; u < 2; ++u) {
                int seg = aseg0 + u;
                sts16_zero(ab + (uint32_t)((seg ^ (grow & 7)) * 16));
            }
        }
        // B: 64B fp16 chunk, XOR-4 swizzle (row stride 64B): seg ^ ((row>>1)&3)
        const unsigned char* bsrc = wp + ((size_t)(kk * CCH + bco) * 8 + cc) * 64;
        const uint32_t bb = sb + buf * STAGE + ASTAGE + (uint32_t)bco * 64u;
#pragma unroll
        for (int u = 0; u < 2; ++u) {
            int seg = bseg0 + u;
            cp16(bb + (uint32_t)((seg ^ ((bco >> 1) & 3)) * 16), bsrc + seg * 16);
        }
        asm volatile("cp.async.commit_group;");
    };

    // prologue: stages 0..2 in flight
    load_chunk(0);
    load_chunk(1);
    load_chunk(2);

    for (int it = 0; it < NITER; ++it) {
        const int rem = NITER - 1 - it;     // groups newer than `it` still issued
        if (rem >= 2)      asm volatile("cp.async.wait_group 2;");
        else if (rem == 1) asm volatile("cp.async.wait_group 1;");
        else               asm volatile("cp.async.wait_group 0;");
        __syncthreads();                    // publish stage it, protect stage it+3

        if (it + 3 < NITER) load_chunk(it + 3);

        const int buf = it & (NSTAGE - 1);
        const uint32_t ab = sb + buf * STAGE;
        const uint32_t bb = ab + ASTAGE;

#pragma unroll
        for (int ks = 0; ks < 2; ++ks) {
            // A fragments (hi and lo) for both m-tiles
            uint32_t ah[2][4], al[2][4];
#pragma unroll
            for (int mt = 0; mt < 2; ++mt) {
                const int m_r  = wm * 32 + mt * 16 + l7 + lq * 8;
                const int sg_h = ks * 2 + lh;
                const uint32_t rbase = ab + (uint32_t)m_r * 128u;
                ldsm4(ah[mt], rbase + (uint32_t)(((sg_h    ) ^ l7) * 16));
                ldsm4(al[mt], rbase + (uint32_t)(((sg_h + 4) ^ l7) * 16));
            }
#pragma unroll
            for (int p = 0; p < 4; ++p) {         // pairs of n-tiles
                const int n_r = wn * 64 + p * 16 + lh * 8 + l7;
                const int sg  = ks * 2 + lq;      // 0..3 within 64B row
                uint32_t bh[4];
                ldsm4(bh, bb + (uint32_t)n_r * 64u
                          + (uint32_t)((sg ^ ((l7 >> 1) & 3)) * 16));
#pragma unroll
                for (int mt = 0; mt < 2; ++mt)
#pragma unroll
                    for (int q = 0; q < 2; ++q) {
                        float* d = acc[mt][p * 2 + q];
                        mma_f16(d, ah[mt], bh[2 * q], bh[2 * q + 1]);  // Ah*Bh
                        mma_f16(d, al[mt], bh[2 * q], bh[2 * q + 1]);  // Al*Bh
                    }
            }
        }
    }

    // ---- epilogue ----
    const int tq = lane >> 2;             // 0..7
    const int tr = lane & 3;              // 0..3
#pragma unroll
    for (int mt = 0; mt < 2; ++mt) {
        const int ra  = row0 + wm * 32 + mt * 16 + tq;
        const int rb2 = ra + 8;
#pragma unroll
        for (int nt = 0; nt < 8; ++nt) {
            const int c = wn * 64 + nt * 8 + tr * 2;
            const float b0 = bias[c], b1 = bias[c + 1];
            if (ra < nrows) {
                float v0 = acc[mt][nt][0] + b0;
                float v1 = acc[mt][nt][1] + b1;
                if (resid) {
                    const float2 rv = *(const float2*)(resid + (size_t)ra * CCH + c);
                    v0 += rv.x; v1 += rv.y;
                }
                *(float2*)(out + (size_t)ra * CCH + c) = make_float2(v0, v1);
            }
            if (rb2 < nrows) {
                float v0 = acc[mt][nt][2] + b0;
                float v1 = acc[mt][nt][3] + b1;
                if (resid) {
                    const float2 rv = *(const float2*)(resid + (size_t)rb2 * CCH + c);
                    v0 += rv.x; v1 += rv.y;
                }
                *(float2*)(out + (size_t)rb2 * CCH + c) = make_float2(v0, v1);
            }
        }
    }
}

// ---------------------------------------------------------------------
extern "C" void kernel_launch(void* const* d_in, const int* in_sizes, int n_in,
                              void* d_out, int out_size)
{
    const float* feats = (const float*)d_in[0];
    const float* emb   = (const float*)d_in[1];
    const int*   jidx  = (const int*)  d_in[2];
    const int*   nbr   = (const int*)  d_in[3];
    const float* gn1w  = (const float*)d_in[4];
    const float* gn1b  = (const float*)d_in[5];
    const float* w1    = (const float*)d_in[6];
    const float* b1    = (const float*)d_in[7];
    const float* embw  = (const float*)d_in[8];
    const float* embb  = (const float*)d_in[9];
    const float* gn2w  = (const float*)d_in[10];
    const float* gn2b  = (const float*)d_in[11];
    const float* w2    = (const float*)d_in[12];
    const float* b2    = (const float*)d_in[13];
    float* out = (float*)d_out;

    unsigned char *xp = nullptr, *w1p = nullptr, *w2p = nullptr;
    cudaGetSymbolAddress((void**)&xp,  g_xp);
    cudaGetSymbolAddress((void**)&w1p, g_w1p);
    cudaGetSymbolAddress((void**)&w2p, g_w2p);

    const int SMEM_CONV = 128 + NSTAGE * STAGE;   // 128 + 128KB
    cudaFuncSetAttribute(convmma_kernel,
                         cudaFuncAttributeMaxDynamicSharedMemorySize, SMEM_CONV);

    const int nblk_norm  = (NROWS * (CCH / 4) + 255) / 256;
    const int nblk_stats = (NROWS + 511) / 512;

    // Launch order keeps conv1 at index 5 (ncu -s 5 -c 1 capture target).
    count_kernel<<<64, 256>>>(jidx, NROWS);                              // 0
    stats_kernel<<<nblk_stats, 256>>>(feats, jidx, NROWS);               // 1
    finalize_kernel<<<1, 128>>>(1);                                      // 2
    norm_pack_kernel<<<nblk_norm, 256>>>(feats, jidx, gn1w, gn1b, xp, 0);// 3
    wpack_kernel<<<KTAP * CCH, 256>>>(w1, w1p);                          // 4
    convmma_kernel<<<NBLK_CONV, 512, SMEM_CONV>>>(xp, nbr, w1p, b1,      // 5
                                                  nullptr, out, NROWS);
    emb_kernel<<<BGR, 512>>>(emb, embw, embb);                           // 6
    stats_kernel<<<nblk_stats, 256>>>(out, jidx, NROWS);                 // 7
    finalize_kernel<<<1, 128>>>(2);                                      // 8
    norm_pack_kernel<<<nblk_norm, 256>>>(out, jidx, gn2w, gn2b, xp, 1);  // 9
    wpack_kernel<<<KTAP * CCH, 256>>>(w2, w2p);                          // 10
    convmma_kernel<<<NBLK_CONV, 512, SMEM_CONV>>>(xp, nbr, w2p, b2,      // 11
                                                  feats, out, NROWS);
}

// round 7
// speedup vs baseline: 2.5397x; 1.4809x over previous
#include <cuda_runtime.h>
#include <cuda_fp16.h>
#include <cstdint>
#include <math.h>

// Problem constants (fixed by the dataset)
#define NROWS 200000
#define CCH   256
#define BGR   4
#define GRP   32
#define KTAP  27
#define CEMB  1024
#define EPSV  1e-5f

#define TILE_M    128
#define CHUNKS    8                    // 32-cin chunks per tap
#define NITER     (KTAP * CHUNKS)      // 216
#define NBLK_CONV ((NROWS + TILE_M - 1) / TILE_M)   // 1563

// packed act row: 8 chunks x [32 fp16 (64B)] = 512 B/row  (hi only, 1-pass)
// packed wgt row: 8 chunks x [32 fp16 (64B)] = 512 B per (tap, cout)
#define ROWB   512
#define ASTAGE 8192                    // 128 rows  * 64B
#define BSTAGE 16384                   // 256 couts * 64B
#define STAGE  (ASTAGE + BSTAGE)       // 24KB per stage
#define NSTAGE 4

// -------- scratch (static __device__ — no runtime allocation) --------
__device__ unsigned char g_xp[(size_t)NROWS * ROWB];        // 102.4 MB packed acts
__device__ unsigned char g_w1p[(size_t)KTAP * CCH * 512];   // 3.5 MB packed weights
__device__ unsigned char g_w2p[(size_t)KTAP * CCH * 512];
__device__ float g_sum[BGR * CCH];
__device__ float g_sq[BGR * CCH];
__device__ float g_mean[BGR * GRP];
__device__ float g_rstd[BGR * GRP];
__device__ int   g_cnt[BGR];
__device__ float g_ss[BGR * 2 * CCH];

// ---------------------------------------------------------------------
__device__ __forceinline__ float silu_f(float v) { return v / (1.0f + expf(-v)); }

__device__ __forceinline__ uint32_t s2u(const void* p) {
    return (uint32_t)__cvta_generic_to_shared(p);
}
__device__ __forceinline__ void cp16(uint32_t dst, const void* src) {
    asm volatile("cp.async.cg.shared.global [%0], [%1], 16;" :: "r"(dst), "l"(src));
}
__device__ __forceinline__ void sts16_zero(uint32_t dst) {
    asm volatile("st.shared.v4.b32 [%0], {%1,%1,%1,%1};" :: "r"(dst), "r"(0u) : "memory");
}
__device__ __forceinline__ void ldsm4(uint32_t* r, uint32_t a) {
    asm volatile("ldmatrix.sync.aligned.m8n8.x4.shared.b16 {%0,%1,%2,%3}, [%4];"
                 : "=r"(r[0]), "=r"(r[1]), "=r"(r[2]), "=r"(r[3]) : "r"(a));
}
__device__ __forceinline__ void mma_f16(float* d, const uint32_t* a,
                                        uint32_t b0, uint32_t b1) {
    asm volatile(
        "mma.sync.aligned.m16n8k16.row.col.f32.f16.f16.f32 "
        "{%0,%1,%2,%3}, {%4,%5,%6,%7}, {%8,%9}, {%0,%1,%2,%3};"
        : "+f"(d[0]), "+f"(d[1]), "+f"(d[2]), "+f"(d[3])
        : "r"(a[0]), "r"(a[1]), "r"(a[2]), "r"(a[3]), "r"(b0), "r"(b1));
}
__device__ __forceinline__ uint32_t pack2h(__half a, __half b) {
    __half2 p = __halves2half2(a, b);
    return *reinterpret_cast<uint32_t*>(&p);
}

// -------- per-grid voxel counts (g_cnt zeroed by finalize phase 2) --------
__global__ void count_kernel(const int* __restrict__ jidx, int n) {
    int c0 = 0, c1 = 0, c2 = 0, c3 = 0;
    for (int i = blockIdx.x * blockDim.x + threadIdx.x; i < n;
         i += gridDim.x * blockDim.x) {
        int b = jidx[i];
        c0 += (b == 0); c1 += (b == 1); c2 += (b == 2); c3 += (b == 3);
    }
    if (c0) atomicAdd(&g_cnt[0], c0);
    if (c1) atomicAdd(&g_cnt[1], c1);
    if (c2) atomicAdd(&g_cnt[2], c2);
    if (c3) atomicAdd(&g_cnt[3], c3);
}

__global__ void stats_kernel(const float* __restrict__ x,
                             const int* __restrict__ jidx, int nrows) {
    const int t = threadIdx.x;                 // channel, blockDim = 256
    int r0 = blockIdx.x * 512;
    int r1 = r0 + 512; if (r1 > nrows) r1 = nrows;
    float s = 0.0f, sq = 0.0f; int cur = -1;
    for (int r = r0; r < r1; ++r) {
        int b = jidx[r];
        if (b != cur) {
            if (cur >= 0) {
                atomicAdd(&g_sum[cur * CCH + t], s);
                atomicAdd(&g_sq[cur * CCH + t], sq);
            }
            cur = b; s = 0.0f; sq = 0.0f;
        }
        float v = x[(size_t)r * CCH + t];
        s += v; sq += v * v;
    }
    if (cur >= 0) {
        atomicAdd(&g_sum[cur * CCH + t], s);
        atomicAdd(&g_sq[cur * CCH + t], sq);
    }
}

// phase 1: mean/rstd + zero g_sum/g_sq for the next stats pass.
// phase 2: same + zero g_cnt (pristine state for next graph replay).
__global__ void finalize_kernel(int phase) {
    int t = threadIdx.x;                       // blockDim = 128
    if (t < BGR * GRP) {
        int b = t / GRP, g = t % GRP;
        float s = 0.0f, sq = 0.0f;
        #pragma unroll
        for (int j = 0; j < 8; ++j) {
            s  += g_sum[b * CCH + g * 8 + j];
            sq += g_sq [b * CCH + g * 8 + j];
        }
        float denom = (float)g_cnt[b] * 8.0f;
        float mean = s / denom;
        float var  = sq / denom - mean * mean;
        g_mean[t] = mean;
        g_rstd[t] = rsqrtf(var + EPSV);
    }
    __syncthreads();
    for (int i = t; i < BGR * CCH; i += 128) { g_sum[i] = 0.0f; g_sq[i] = 0.0f; }
    if (phase == 2 && t < BGR) g_cnt[t] = 0;
}

// -------- GN + SiLU -> packed fp16 rows (film=0: GN1; film=1: GN2+FiLM) --
__global__ void norm_pack_kernel(const float* __restrict__ x,
                                 const int* __restrict__ jidx,
                                 const float* __restrict__ w,
                                 const float* __restrict__ bb,
                                 unsigned char* __restrict__ xp, int film) {
    size_t i4 = (size_t)blockIdx.x * blockDim.x + threadIdx.x;
    if (i4 >= (size_t)NROWS * (CCH / 4)) return;
    int n = (int)(i4 >> 6);
    int c = ((int)i4 & 63) * 4;
    int b = jidx[n];
    int g = c >> 3;
    float mean = g_mean[b * GRP + g];
    float rstd = g_rstd[b * GRP + g];
    float4 xv = *(const float4*)(x + i4 * 4);
    float4 wv = *(const float4*)(w + c);
    float4 bv = *(const float4*)(bb + c);
    float o[4];
    o[0] = (xv.x - mean) * rstd * wv.x + bv.x;
    o[1] = (xv.y - mean) * rstd * wv.y + bv.y;
    o[2] = (xv.z - mean) * rstd * wv.z + bv.z;
    o[3] = (xv.w - mean) * rstd * wv.w + bv.w;
    if (film) {
        float4 sc = *(const float4*)(g_ss + b * (2 * CCH) + c);
        float4 sh = *(const float4*)(g_ss + b * (2 * CCH) + CCH + c);
        o[0] = o[0] * (1.0f + sc.x) + sh.x;
        o[1] = o[1] * (1.0f + sc.y) + sh.y;
        o[2] = o[2] * (1.0f + sc.z) + sh.z;
        o[3] = o[3] * (1.0f + sc.w) + sh.w;
    }
    __half h[4];
    #pragma unroll
    for (int j = 0; j < 4; ++j) h[j] = __float2half(silu_f(o[j]));
    size_t base = (size_t)n * ROWB + (size_t)(c >> 5) * 64 + (size_t)(c & 31) * 2;
    *(uint2*)(xp + base) = make_uint2(pack2h(h[0], h[1]), pack2h(h[2], h[3]));
}

// -------- pack W[k][cin][cout] -> wp[(k*256+cout)*8 + cin/32] (64B, fp16) -----
__global__ void wpack_kernel(const float* __restrict__ W,
                             unsigned char* __restrict__ wp) {
    int bid = blockIdx.x;               // 0 .. 27*256-1
    int k = bid >> 8, cout = bid & 255;
    int cin = threadIdx.x;              // 0..255
    float v = W[((size_t)(k * CCH + cin)) * CCH + cout];
    __half h = __float2half(v);
    size_t base = ((size_t)(k * CCH + cout) * 8 + (cin >> 5)) * 64 + (size_t)(cin & 31) * 2;
    *(__half*)(wp + base) = h;
}

// -------- embedding MLP --------
__global__ void emb_kernel(const float* __restrict__ emb,
                           const float* __restrict__ ew,
                           const float* __restrict__ eb) {
    __shared__ float se[CEMB];
    int b = blockIdx.x;
    int t = threadIdx.x;                // blockDim = 512
    for (int i = t; i < CEMB; i += 512) se[i] = silu_f(emb[b * CEMB + i]);
    __syncthreads();
    float acc = eb[t];
    for (int i = 0; i < CEMB; ++i)
        acc += se[i] * ew[i * (2 * CCH) + t];
    g_ss[b * (2 * CCH) + t] = acc;
}

// ================= HMMA sparse-conv GEMM (fp16, 1-pass) =================
// CTA: 512 thr, tile 128 rows x 256 cout. Warp grid 4m x 4n, warp tile 32x64.
// D = fp16(A) * fp16(B) with fp32 accum (elem err ~2^-11 each side).
// 4-stage cp.async pipeline, one __syncthreads per iteration:
//   wait_group -> sync -> issue loads(it+3) -> compute(it)
__global__ void __launch_bounds__(512, 1) convmma_kernel(
    const unsigned char* __restrict__ xp, const int* __restrict__ nbr,
    const unsigned char* __restrict__ wp, const float* __restrict__ bias,
    const float* __restrict__ resid, float* __restrict__ out, int nrows)
{
    extern __shared__ unsigned char dsm[];
    const int tid  = threadIdx.x;
    const int lane = tid & 31;
    const int wid  = tid >> 5;
    const int wm   = wid & 3;            // warp m-tile (32 rows each)
    const int wn   = wid >> 2;           // warp n-tile (64 couts each)
    const int row0 = blockIdx.x * TILE_M;

    uint32_t sb = (s2u(dsm) + 127u) & ~127u;

    // ldmatrix lane decomposition
    const int l7 = lane & 7;
    const int lq = (lane >> 3) & 1;
    const int lh = (lane >> 4) & 1;

    // gather mapping: A rows (thread t -> row t>>2, 1 seg of 16B),
    //                 B couts (thread t -> cout t>>1, 2 segs of 16B)
    const int grow  = tid >> 2;
    const bool gok  = (row0 + grow) < nrows;
    const int aseg  = tid & 3;
    const int bco   = tid >> 1;
    const int bseg0 = (tid & 1) * 2;

    float acc[2][8][4];
#pragma unroll
    for (int mt = 0; mt < 2; ++mt)
#pragma unroll
        for (int nt = 0; nt < 8; ++nt)
#pragma unroll
            for (int q = 0; q < 4; ++q) acc[mt][nt][q] = 0.0f;

    int gidx = -1;
    auto load_chunk = [&](int j) {
        const int kk = j >> 3, cc = j & 7, buf = j & (NSTAGE - 1);
        if (cc == 0) gidx = gok ? nbr[(size_t)(row0 + grow) * KTAP + kk] : -1;
        // A: 64B chunk, XOR-4 swizzle on 64B rows: seg ^ ((row>>1)&3)
        const uint32_t ab = sb + buf * STAGE + (uint32_t)grow * 64u
                          + (uint32_t)((aseg ^ ((grow >> 1) & 3)) * 16);
        if (gidx >= 0)
            cp16(ab, xp + (size_t)gidx * ROWB + (size_t)cc * 64 + aseg * 16);
        else
            sts16_zero(ab);
        // B: 64B fp16 chunk, same swizzle
        const unsigned char* bsrc = wp + ((size_t)(kk * CCH + bco) * 8 + cc) * 64;
        const uint32_t bb = sb + buf * STAGE + ASTAGE + (uint32_t)bco * 64u;
#pragma unroll
        for (int u = 0; u < 2; ++u) {
            int seg = bseg0 + u;
            cp16(bb + (uint32_t)((seg ^ ((bco >> 1) & 3)) * 16), bsrc + seg * 16);
        }
        asm volatile("cp.async.commit_group;");
    };

    // prologue: stages 0..2 in flight
    load_chunk(0);
    load_chunk(1);
    load_chunk(2);

    for (int it = 0; it < NITER; ++it) {
        const int rem = NITER - 1 - it;     // groups newer than `it` still issued
        if (rem >= 2)      asm volatile("cp.async.wait_group 2;");
        else if (rem == 1) asm volatile("cp.async.wait_group 1;");
        else               asm volatile("cp.async.wait_group 0;");
        __syncthreads();                    // publish stage it, protect stage it+3

        if (it + 3 < NITER) load_chunk(it + 3);

        const int buf = it & (NSTAGE - 1);
        const uint32_t ab = sb + buf * STAGE;
        const uint32_t bb = ab + ASTAGE;

#pragma unroll
        for (int ks = 0; ks < 2; ++ks) {
            // A fragments for both m-tiles
            uint32_t ah[2][4];
#pragma unroll
            for (int mt = 0; mt < 2; ++mt) {
                const int m_r = wm * 32 + mt * 16 + l7 + lq * 8;
                const int sg  = ks * 2 + lh;      // 0..3 within 64B row
                ldsm4(ah[mt], ab + (uint32_t)m_r * 64u
                            + (uint32_t)((sg ^ ((m_r >> 1) & 3)) * 16));
            }
#pragma unroll
            for (int p = 0; p < 4; ++p) {         // pairs of n-tiles
                const int n_r = wn * 64 + p * 16 + lh * 8 + l7;
                const int sg  = ks * 2 + lq;
                uint32_t bh[4];
                ldsm4(bh, bb + (uint32_t)n_r * 64u
                          + (uint32_t)((sg ^ ((n_r >> 1) & 3)) * 16));
#pragma unroll
                for (int mt = 0; mt < 2; ++mt)
#pragma unroll
                    for (int q = 0; q < 2; ++q)
                        mma_f16(acc[mt][p * 2 + q], ah[mt], bh[2 * q], bh[2 * q + 1]);
            }
        }
    }

    // ---- epilogue ----
    const int tq = lane >> 2;             // 0..7
    const int tr = lane & 3;              // 0..3
#pragma unroll
    for (int mt = 0; mt < 2; ++mt) {
        const int ra  = row0 + wm * 32 + mt * 16 + tq;
        const int rb2 = ra + 8;
#pragma unroll
        for (int nt = 0; nt < 8; ++nt) {
            const int c = wn * 64 + nt * 8 + tr * 2;
            const float b0 = bias[c], b1 = bias[c + 1];
            if (ra < nrows) {
                float v0 = acc[mt][nt][0] + b0;
                float v1 = acc[mt][nt][1] + b1;
                if (resid) {
                    const float2 rv = *(const float2*)(resid + (size_t)ra * CCH + c);
                    v0 += rv.x; v1 += rv.y;
                }
                *(float2*)(out + (size_t)ra * CCH + c) = make_float2(v0, v1);
            }
            if (rb2 < nrows) {
                float v0 = acc[mt][nt][2] + b0;
                float v1 = acc[mt][nt][3] + b1;
                if (resid) {
                    const float2 rv = *(const float2*)(resid + (size_t)rb2 * CCH + c);
                    v0 += rv.x; v1 += rv.y;
                }
                *(float2*)(out + (size_t)rb2 * CCH + c) = make_float2(v0, v1);
            }
        }
    }
}

// ---------------------------------------------------------------------
extern "C" void kernel_launch(void* const* d_in, const int* in_sizes, int n_in,
                              void* d_out, int out_size)
{
    const float* feats = (const float*)d_in[0];
    const float* emb   = (const float*)d_in[1];
    const int*   jidx  = (const int*)  d_in[2];
    const int*   nbr   = (const int*)  d_in[3];
    const float* gn1w  = (const float*)d_in[4];
    const float* gn1b  = (const float*)d_in[5];
    const float* w1    = (const float*)d_in[6];
    const float* b1    = (const float*)d_in[7];
    const float* embw  = (const float*)d_in[8];
    const float* embb  = (const float*)d_in[9];
    const float* gn2w  = (const float*)d_in[10];
    const float* gn2b  = (const float*)d_in[11];
    const float* w2    = (const float*)d_in[12];
    const float* b2    = (const float*)d_in[13];
    float* out = (float*)d_out;

    unsigned char *xp = nullptr, *w1p = nullptr, *w2p = nullptr;
    cudaGetSymbolAddress((void**)&xp,  g_xp);
    cudaGetSymbolAddress((void**)&w1p, g_w1p);
    cudaGetSymbolAddress((void**)&w2p, g_w2p);

    const int SMEM_CONV = 128 + NSTAGE * STAGE;   // 128 + 96KB
    cudaFuncSetAttribute(convmma_kernel,
                         cudaFuncAttributeMaxDynamicSharedMemorySize, SMEM_CONV);

    const int nblk_norm  = (NROWS * (CCH / 4) + 255) / 256;
    const int nblk_stats = (NROWS + 511) / 512;

    // Launch order keeps conv1 at index 5 (ncu -s 5 -c 1 capture target).
    count_kernel<<<64, 256>>>(jidx, NROWS);                              // 0
    stats_kernel<<<nblk_stats, 256>>>(feats, jidx, NROWS);               // 1
    finalize_kernel<<<1, 128>>>(1);                                      // 2
    norm_pack_kernel<<<nblk_norm, 256>>>(feats, jidx, gn1w, gn1b, xp, 0);// 3
    wpack_kernel<<<KTAP * CCH, 256>>>(w1, w1p);                          // 4
    convmma_kernel<<<NBLK_CONV, 512, SMEM_CONV>>>(xp, nbr, w1p, b1,      // 5
                                                  nullptr, out, NROWS);
    emb_kernel<<<BGR, 512>>>(emb, embw, embb);                           // 6
    stats_kernel<<<nblk_stats, 256>>>(out, jidx, NROWS);                 // 7
    finalize_kernel<<<1, 128>>>(2);                                      // 8
    norm_pack_kernel<<<nblk_norm, 256>>>(out, jidx, gn2w, gn2b, xp, 1);  // 9
    wpack_kernel<<<KTAP * CCH, 256>>>(w2, w2p);                          // 10
    convmma_kernel<<<NBLK_CONV, 512, SMEM_CONV>>>(xp, nbr, w2p, b2,      // 11
                                                  feats, out, NROWS);
}

// round 8
// speedup vs baseline: 2.7291x; 1.0746x over previous
#include <cuda_runtime.h>
#include <cuda_fp16.h>
#include <cstdint>
#include <math.h>

// Problem constants (fixed by the dataset)
#define NROWS 200000
#define CCH   256
#define BGR   4
#define GRP   32
#define KTAP  27
#define CEMB  1024
#define EPSV  1e-5f

#define TILE_M    128
#define CHUNKS    4                    // 64-cin chunks per tap
#define NITER     (KTAP * CHUNKS)      // 108
#define NBLK_CONV ((NROWS + TILE_M - 1) / TILE_M)   // 1563

// packed act row: 8x 64B fp16 chunks = 512 B/row (64-cin iter reads 128B)
// packed wgt row: 8x 64B fp16 chunks = 512 B per (tap, cout)
#define ROWB   512
#define ASTAGE 16384                   // 128 rows  * 128B
#define BSTAGE 32768                   // 256 couts * 128B
#define STAGE  (ASTAGE + BSTAGE)       // 48KB per stage
#define NSTAGE 3

// -------- scratch (static __device__ — no runtime allocation) --------
__device__ unsigned char g_xp[(size_t)NROWS * ROWB];        // 102.4 MB packed acts
__device__ unsigned char g_w1p[(size_t)KTAP * CCH * 512];   // 3.5 MB packed weights
__device__ unsigned char g_w2p[(size_t)KTAP * CCH * 512];
__device__ float g_sum[BGR * CCH];
__device__ float g_sq[BGR * CCH];
__device__ float g_mean[BGR * GRP];
__device__ float g_rstd[BGR * GRP];
__device__ int   g_cnt[BGR];
__device__ float g_ss[BGR * 2 * CCH];

// ---------------------------------------------------------------------
__device__ __forceinline__ float silu_f(float v) { return v / (1.0f + expf(-v)); }

__device__ __forceinline__ uint32_t s2u(const void* p) {
    return (uint32_t)__cvta_generic_to_shared(p);
}
__device__ __forceinline__ void cp16(uint32_t dst, const void* src) {
    asm volatile("cp.async.cg.shared.global [%0], [%1], 16;" :: "r"(dst), "l"(src));
}
__device__ __forceinline__ void sts16_zero(uint32_t dst) {
    asm volatile("st.shared.v4.b32 [%0], {%1,%1,%1,%1};" :: "r"(dst), "r"(0u) : "memory");
}
__device__ __forceinline__ void ldsm4(uint32_t* r, uint32_t a) {
    asm volatile("ldmatrix.sync.aligned.m8n8.x4.shared.b16 {%0,%1,%2,%3}, [%4];"
                 : "=r"(r[0]), "=r"(r[1]), "=r"(r[2]), "=r"(r[3]) : "r"(a));
}
__device__ __forceinline__ void mma_f16(float* d, const uint32_t* a,
                                        uint32_t b0, uint32_t b1) {
    asm volatile(
        "mma.sync.aligned.m16n8k16.row.col.f32.f16.f16.f32 "
        "{%0,%1,%2,%3}, {%4,%5,%6,%7}, {%8,%9}, {%0,%1,%2,%3};"
        : "+f"(d[0]), "+f"(d[1]), "+f"(d[2]), "+f"(d[3])
        : "r"(a[0]), "r"(a[1]), "r"(a[2]), "r"(a[3]), "r"(b0), "r"(b1));
}
__device__ __forceinline__ uint32_t pack2h(__half a, __half b) {
    __half2 p = __halves2half2(a, b);
    return *reinterpret_cast<uint32_t*>(&p);
}

// -------- per-grid voxel counts (g_cnt zeroed by finalize phase 2) --------
__global__ void count_kernel(const int* __restrict__ jidx, int n) {
    int c0 = 0, c1 = 0, c2 = 0, c3 = 0;
    for (int i = blockIdx.x * blockDim.x + threadIdx.x; i < n;
         i += gridDim.x * blockDim.x) {
        int b = jidx[i];
        c0 += (b == 0); c1 += (b == 1); c2 += (b == 2); c3 += (b == 3);
    }
    if (c0) atomicAdd(&g_cnt[0], c0);
    if (c1) atomicAdd(&g_cnt[1], c1);
    if (c2) atomicAdd(&g_cnt[2], c2);
    if (c3) atomicAdd(&g_cnt[3], c3);
}

__global__ void stats_kernel(const float* __restrict__ x,
                             const int* __restrict__ jidx, int nrows) {
    const int t = threadIdx.x;                 // channel, blockDim = 256
    int r0 = blockIdx.x * 512;
    int r1 = r0 + 512; if (r1 > nrows) r1 = nrows;
    float s = 0.0f, sq = 0.0f; int cur = -1;
    for (int r = r0; r < r1; ++r) {
        int b = jidx[r];
        if (b != cur) {
            if (cur >= 0) {
                atomicAdd(&g_sum[cur * CCH + t], s);
                atomicAdd(&g_sq[cur * CCH + t], sq);
            }
            cur = b; s = 0.0f; sq = 0.0f;
        }
        float v = x[(size_t)r * CCH + t];
        s += v; sq += v * v;
    }
    if (cur >= 0) {
        atomicAdd(&g_sum[cur * CCH + t], s);
        atomicAdd(&g_sq[cur * CCH + t], sq);
    }
}

// phase 1: mean/rstd + zero g_sum/g_sq for the next stats pass.
// phase 2: same + zero g_cnt (pristine state for next graph replay).
__global__ void finalize_kernel(int phase) {
    int t = threadIdx.x;                       // blockDim = 128
    if (t < BGR * GRP) {
        int b = t / GRP, g = t % GRP;
        float s = 0.0f, sq = 0.0f;
        #pragma unroll
        for (int j = 0; j < 8; ++j) {
            s  += g_sum[b * CCH + g * 8 + j];
            sq += g_sq [b * CCH + g * 8 + j];
        }
        float denom = (float)g_cnt[b] * 8.0f;
        float mean = s / denom;
        float var  = sq / denom - mean * mean;
        g_mean[t] = mean;
        g_rstd[t] = rsqrtf(var + EPSV);
    }
    __syncthreads();
    for (int i = t; i < BGR * CCH; i += 128) { g_sum[i] = 0.0f; g_sq[i] = 0.0f; }
    if (phase == 2 && t < BGR) g_cnt[t] = 0;
}

// -------- GN + SiLU -> packed fp16 rows (film=0: GN1; film=1: GN2+FiLM) --
__global__ void norm_pack_kernel(const float* __restrict__ x,
                                 const int* __restrict__ jidx,
                                 const float* __restrict__ w,
                                 const float* __restrict__ bb,
                                 unsigned char* __restrict__ xp, int film) {
    size_t i4 = (size_t)blockIdx.x * blockDim.x + threadIdx.x;
    if (i4 >= (size_t)NROWS * (CCH / 4)) return;
    int n = (int)(i4 >> 6);
    int c = ((int)i4 & 63) * 4;
    int b = jidx[n];
    int g = c >> 3;
    float mean = g_mean[b * GRP + g];
    float rstd = g_rstd[b * GRP + g];
    float4 xv = *(const float4*)(x + i4 * 4);
    float4 wv = *(const float4*)(w + c);
    float4 bv = *(const float4*)(bb + c);
    float o[4];
    o[0] = (xv.x - mean) * rstd * wv.x + bv.x;
    o[1] = (xv.y - mean) * rstd * wv.y + bv.y;
    o[2] = (xv.z - mean) * rstd * wv.z + bv.z;
    o[3] = (xv.w - mean) * rstd * wv.w + bv.w;
    if (film) {
        float4 sc = *(const float4*)(g_ss + b * (2 * CCH) + c);
        float4 sh = *(const float4*)(g_ss + b * (2 * CCH) + CCH + c);
        o[0] = o[0] * (1.0f + sc.x) + sh.x;
        o[1] = o[1] * (1.0f + sc.y) + sh.y;
        o[2] = o[2] * (1.0f + sc.z) + sh.z;
        o[3] = o[3] * (1.0f + sc.w) + sh.w;
    }
    __half h[4];
    #pragma unroll
    for (int j = 0; j < 4; ++j) h[j] = __float2half(silu_f(o[j]));
    size_t base = (size_t)n * ROWB + (size_t)(c >> 5) * 64 + (size_t)(c & 31) * 2;
    *(uint2*)(xp + base) = make_uint2(pack2h(h[0], h[1]), pack2h(h[2], h[3]));
}

// -------- pack W[k][cin][cout] -> wp[(k*256+cout)*8 + cin/32] (64B, fp16) -----
__global__ void wpack_kernel(const float* __restrict__ W,
                             unsigned char* __restrict__ wp) {
    int bid = blockIdx.x;               // 0 .. 27*256-1
    int k = bid >> 8, cout = bid & 255;
    int cin = threadIdx.x;              // 0..255
    float v = W[((size_t)(k * CCH + cin)) * CCH + cout];
    __half h = __float2half(v);
    size_t base = ((size_t)(k * CCH + cout) * 8 + (cin >> 5)) * 64 + (size_t)(cin & 31) * 2;
    *(__half*)(wp + base) = h;
}

// -------- embedding MLP --------
__global__ void emb_kernel(const float* __restrict__ emb,
                           const float* __restrict__ ew,
                           const float* __restrict__ eb) {
    __shared__ float se[CEMB];
    int b = blockIdx.x;
    int t = threadIdx.x;                // blockDim = 512
    for (int i = t; i < CEMB; i += 512) se[i] = silu_f(emb[b * CEMB + i]);
    __syncthreads();
    float acc = eb[t];
    for (int i = 0; i < CEMB; ++i)
        acc += se[i] * ew[i * (2 * CCH) + t];
    g_ss[b * (2 * CCH) + t] = acc;
}

// ================= HMMA sparse-conv GEMM (fp16, 64-cin chunks) =================
// CTA: 512 thr, tile 128 rows x 256 cout. Warp grid 4m x 4n, warp tile 32x64.
// 108 iterations of 64 cin each; 3-stage cp.async pipeline, one barrier/iter:
//   wait_group -> sync -> issue loads(it+2) -> compute(it)  [4 k16 steps]
__global__ void __launch_bounds__(512, 1) convmma_kernel(
    const unsigned char* __restrict__ xp, const int* __restrict__ nbr,
    const unsigned char* __restrict__ wp, const float* __restrict__ bias,
    const float* __restrict__ resid, float* __restrict__ out, int nrows)
{
    extern __shared__ unsigned char dsm[];
    const int tid  = threadIdx.x;
    const int lane = tid & 31;
    const int wid  = tid >> 5;
    const int wm   = wid & 3;            // warp m-tile (32 rows each)
    const int wn   = wid >> 2;           // warp n-tile (64 couts each)
    const int row0 = blockIdx.x * TILE_M;

    uint32_t sb = (s2u(dsm) + 127u) & ~127u;

    // ldmatrix lane decomposition
    const int l7 = lane & 7;
    const int lq = (lane >> 3) & 1;
    const int lh = (lane >> 4) & 1;

    // gather mapping: A rows (thread t -> row t>>2, 2 segs of 16B),
    //                 B couts (thread t -> cout t>>1, 4 segs of 16B)
    const int grow  = tid >> 2;
    const bool gok  = (row0 + grow) < nrows;
    const int aseg0 = (tid & 3) * 2;
    const int bco   = tid >> 1;
    const int bseg0 = (tid & 1) * 4;

    float acc[2][8][4];
#pragma unroll
    for (int mt = 0; mt < 2; ++mt)
#pragma unroll
        for (int nt = 0; nt < 8; ++nt)
#pragma unroll
            for (int q = 0; q < 4; ++q) acc[mt][nt][q] = 0.0f;

    int gidx = -1;
    auto load_chunk = [&](int j) {
        const int kk = j >> 2, cc = j & 3;            // tap, 128B chunk
        int buf = j % NSTAGE;
        if (cc == 0) gidx = gok ? nbr[(size_t)(row0 + grow) * KTAP + kk] : -1;
        // A: 128B chunk (two contiguous 64B gmem chunks), XOR-8 swizzle
        const uint32_t ab = sb + buf * STAGE + (uint32_t)grow * 128u;
        if (gidx >= 0) {
            const unsigned char* src = xp + (size_t)gidx * ROWB + (size_t)cc * 128;
#pragma unroll
            for (int u = 0; u < 2; ++u) {
                int seg = aseg0 + u;
                cp16(ab + (uint32_t)((seg ^ (grow & 7)) * 16), src + seg * 16);
            }
        } else {
#pragma unroll
            for (int u = 0; u < 2; ++u) {
                int seg = aseg0 + u;
                sts16_zero(ab + (uint32_t)((seg ^ (grow & 7)) * 16));
            }
        }
        // B: 128B chunk per cout, XOR-8 swizzle
        const unsigned char* bsrc = wp + (size_t)(kk * CCH + bco) * 512 + (size_t)cc * 128;
        const uint32_t bb = sb + buf * STAGE + ASTAGE + (uint32_t)bco * 128u;
#pragma unroll
        for (int u = 0; u < 4; ++u) {
            int seg = bseg0 + u;
            cp16(bb + (uint32_t)((seg ^ (bco & 7)) * 16), bsrc + seg * 16);
        }
        asm volatile("cp.async.commit_group;");
    };

    // prologue: stages 0 and 1 in flight
    load_chunk(0);
    load_chunk(1);

    for (int it = 0; it < NITER; ++it) {
        if (it + 1 < NITER) asm volatile("cp.async.wait_group 1;");
        else                asm volatile("cp.async.wait_group 0;");
        __syncthreads();                    // publish stage it, protect stage it+2

        if (it + 2 < NITER) load_chunk(it + 2);

        const int buf = it % NSTAGE;
        const uint32_t ab = sb + buf * STAGE;
        const uint32_t bb = ab + ASTAGE;

#pragma unroll
        for (int ks = 0; ks < 4; ++ks) {      // 4 k16 steps within 128B rows
            // A fragments for both m-tiles
            uint32_t ah[2][4];
#pragma unroll
            for (int mt = 0; mt < 2; ++mt) {
                const int m_r = wm * 32 + mt * 16 + l7 + lq * 8;
                const int sg  = ks * 2 + lh;          // granule 0..7
                ldsm4(ah[mt], ab + (uint32_t)m_r * 128u
                            + (uint32_t)((sg ^ l7) * 16));
            }
#pragma unroll
            for (int p = 0; p < 4; ++p) {             // pairs of n-tiles
                const int n_r = wn * 64 + p * 16 + lh * 8 + l7;
                const int sg  = ks * 2 + lq;
                uint32_t bh[4];
                ldsm4(bh, bb + (uint32_t)n_r * 128u
                          + (uint32_t)((sg ^ l7) * 16));
#pragma unroll
                for (int mt = 0; mt < 2; ++mt)
#pragma unroll
                    for (int q = 0; q < 2; ++q)
                        mma_f16(acc[mt][p * 2 + q], ah[mt], bh[2 * q], bh[2 * q + 1]);
            }
        }
    }

    // ---- epilogue ----
    const int tq = lane >> 2;             // 0..7
    const int tr = lane & 3;              // 0..3
#pragma unroll
    for (int mt = 0; mt < 2; ++mt) {
        const int ra  = row0 + wm * 32 + mt * 16 + tq;
        const int rb2 = ra + 8;
#pragma unroll
        for (int nt = 0; nt < 8; ++nt) {
            const int c = wn * 64 + nt * 8 + tr * 2;
            const float b0 = bias[c], b1 = bias[c + 1];
            if (ra < nrows) {
                float v0 = acc[mt][nt][0] + b0;
                float v1 = acc[mt][nt][1] + b1;
                if (resid) {
                    const float2 rv = *(const float2*)(resid + (size_t)ra * CCH + c);
                    v0 += rv.x; v1 += rv.y;
                }
                *(float2*)(out + (size_t)ra * CCH + c) = make_float2(v0, v1);
            }
            if (rb2 < nrows) {
                float v0 = acc[mt][nt][2] + b0;
                float v1 = acc[mt][nt][3] + b1;
                if (resid) {
                    const float2 rv = *(const float2*)(resid + (size_t)rb2 * CCH + c);
                    v0 += rv.x; v1 += rv.y;
                }
                *(float2*)(out + (size_t)rb2 * CCH + c) = make_float2(v0, v1);
            }
        }
    }
}

// ---------------------------------------------------------------------
extern "C" void kernel_launch(void* const* d_in, const int* in_sizes, int n_in,
                              void* d_out, int out_size)
{
    const float* feats = (const float*)d_in[0];
    const float* emb   = (const float*)d_in[1];
    const int*   jidx  = (const int*)  d_in[2];
    const int*   nbr   = (const int*)  d_in[3];
    const float* gn1w  = (const float*)d_in[4];
    const float* gn1b  = (const float*)d_in[5];
    const float* w1    = (const float*)d_in[6];
    const float* b1    = (const float*)d_in[7];
    const float* embw  = (const float*)d_in[8];
    const float* embb  = (const float*)d_in[9];
    const float* gn2w  = (const float*)d_in[10];
    const float* gn2b  = (const float*)d_in[11];
    const float* w2    = (const float*)d_in[12];
    const float* b2    = (const float*)d_in[13];
    float* out = (float*)d_out;

    unsigned char *xp = nullptr, *w1p = nullptr, *w2p = nullptr;
    cudaGetSymbolAddress((void**)&xp,  g_xp);
    cudaGetSymbolAddress((void**)&w1p, g_w1p);
    cudaGetSymbolAddress((void**)&w2p, g_w2p);

    const int SMEM_CONV = 128 + NSTAGE * STAGE;   // 128 + 144KB
    cudaFuncSetAttribute(convmma_kernel,
                         cudaFuncAttributeMaxDynamicSharedMemorySize, SMEM_CONV);

    const int nblk_norm  = (NROWS * (CCH / 4) + 255) / 256;
    const int nblk_stats = (NROWS + 511) / 512;

    // Launch order keeps conv1 at index 5 (ncu -s 5 -c 1 capture target).
    count_kernel<<<64, 256>>>(jidx, NROWS);                              // 0
    stats_kernel<<<nblk_stats, 256>>>(feats, jidx, NROWS);               // 1
    finalize_kernel<<<1, 128>>>(1);                                      // 2
    norm_pack_kernel<<<nblk_norm, 256>>>(feats, jidx, gn1w, gn1b, xp, 0);// 3
    wpack_kernel<<<KTAP * CCH, 256>>>(w1, w1p);                          // 4
    convmma_kernel<<<NBLK_CONV, 512, SMEM_CONV>>>(xp, nbr, w1p, b1,      // 5
                                                  nullptr, out, NROWS);
    emb_kernel<<<BGR, 512>>>(emb, embw, embb);                           // 6
    stats_kernel<<<nblk_stats, 256>>>(out, jidx, NROWS);                 // 7
    finalize_kernel<<<1, 128>>>(2);                                      // 8
    norm_pack_kernel<<<nblk_norm, 256>>>(out, jidx, gn2w, gn2b, xp, 1);  // 9
    wpack_kernel<<<KTAP * CCH, 256>>>(w2, w2p);                          // 10
    convmma_kernel<<<NBLK_CONV, 512, SMEM_CONV>>>(xp, nbr, w2p, b2,      // 11
                                                  feats, out, NROWS);
}